// round 7
// baseline (speedup 1.0000x reference)
#include <cuda_runtime.h>
#include <math.h>

// Problem constants
#define Bq  4
#define Tq  2048
#define Dq  1024
#define Hq  16
#define DKq 64
#define DVq 64
#define MT  (Bq*Tq)   // 8192 rows

// ---------------- scratch (device globals: allocation-free) ----------------
__device__ float g_xnorm[MT*Dq];
__device__ float g_q[MT*Dq];
__device__ float g_k[MT*Dq];
__device__ float g_v[MT*Dq];
__device__ float g_g[MT*Dq];
__device__ float g_qc[MT*Dq];
__device__ float g_kc[MT*Dq];
__device__ float g_vc[MT*Dq];
__device__ float g_beta[MT*Hq];
__device__ float g_decay[MT*Hq];
__device__ float g_o[MT*Dq];
__device__ float g_y[MT*Dq];

// ---------------- RMSNorm over D=1024 ----------------
__global__ void rmsnorm_kernel(const float* __restrict__ x, const float* __restrict__ w) {
    int row = blockIdx.x;
    int tid = threadIdx.x;  // 256 threads, 4 floats each
    const float4* xr = (const float4*)(x + (size_t)row * Dq);
    float4 v = xr[tid];
    float ss = v.x*v.x + v.y*v.y + v.z*v.z + v.w*v.w;
    #pragma unroll
    for (int o = 16; o; o >>= 1) ss += __shfl_xor_sync(0xffffffffu, ss, o);
    __shared__ float red[8];
    __shared__ float s_inv;
    int warp = tid >> 5, lane = tid & 31;
    if (lane == 0) red[warp] = ss;
    __syncthreads();
    if (tid == 0) {
        float t2 = 0.f;
        #pragma unroll
        for (int i = 0; i < 8; i++) t2 += red[i];
        s_inv = rsqrtf(t2 * (1.0f / Dq) + 1e-5f);
    }
    __syncthreads();
    float inv = s_inv;
    float4 wv = ((const float4*)w)[tid];
    float4 o4 = make_float4(v.x*inv*wv.x, v.y*inv*wv.y, v.z*inv*wv.z, v.w*inv*wv.w);
    ((float4*)(g_xnorm + (size_t)row * Dq))[tid] = o4;
}

// ---------------- tf32 tensor-core GEMM 128x128, K-step 32 ----------------
// C[M,N] = A[M,K] @ B[K,N] (+resid). fp32 in/out, tf32 mma, fp32 accumulate.
__device__ __forceinline__ unsigned f2tf32(float f) {
    unsigned u;
    asm("cvt.rna.tf32.f32 %0, %1;" : "=r"(u) : "f"(f));
    return u;
}

#define PADL 136   // 128 cols + 8 pad (keeps 16B alignment; enables swizzle)

__device__ __forceinline__ void tgemm_body(
    const float* __restrict__ A, const float* __restrict__ B,
    float* __restrict__ C, const float* __restrict__ resid,
    int K, int N, int bm, int bn)
{
    __shared__ unsigned As[32][PADL];   // [k][row ^ swz]
    __shared__ unsigned Bs[32][PADL];   // [k][n]
    const int tid  = threadIdx.x;
    const int lane = tid & 31;
    const int warp = tid >> 5;
    const int wm = warp & 1, wn = warp >> 1;   // 2 x 4 warp grid
    const int g = lane >> 2, tig = lane & 3;

    float acc[4][4][4];
    #pragma unroll
    for (int tm = 0; tm < 4; tm++)
        #pragma unroll
        for (int tn = 0; tn < 4; tn++)
            #pragma unroll
            for (int r = 0; r < 4; r++) acc[tm][tn][r] = 0.f;

    // global-load mapping
    const int arow = tid >> 3;              // 0..31 (+32*i)
    const int ak4  = (tid & 7) * 4;         // k column group 0..28
    const int bk   = tid >> 5;              // 0..7 (+8*i)
    const int bn4  = (tid & 31) * 4;        // 0..124
    const int asw  = (tid & 7) << 2;        // A store swizzle: ((k>>2)&7)<<2, k>>2 == tid&7

    const float* Ap = A + (size_t)(bm + arow) * K + ak4;
    const float* Bp = B + (size_t)bk * N + bn + bn4;

    float4 pa[4], pb[4];
    #pragma unroll
    for (int i = 0; i < 4; i++) {
        pa[i] = *(const float4*)(Ap + (size_t)(32 * i) * K);
        pb[i] = *(const float4*)(Bp + (size_t)(8 * i) * N);
    }

    for (int k0 = 0; k0 < K; k0 += 32) {
        #pragma unroll
        for (int i = 0; i < 4; i++) {
            int r = arow + 32 * i;
            int cs = r ^ asw;
            As[ak4 + 0][cs] = f2tf32(pa[i].x);
            As[ak4 + 1][cs] = f2tf32(pa[i].y);
            As[ak4 + 2][cs] = f2tf32(pa[i].z);
            As[ak4 + 3][cs] = f2tf32(pa[i].w);
            *(uint4*)&Bs[bk + 8 * i][bn4] =
                make_uint4(f2tf32(pb[i].x), f2tf32(pb[i].y),
                           f2tf32(pb[i].z), f2tf32(pb[i].w));
        }
        __syncthreads();
        if (k0 + 32 < K) {
            #pragma unroll
            for (int i = 0; i < 4; i++) {
                pa[i] = *(const float4*)(Ap + (k0 + 32) + (size_t)(32 * i) * K);
                pb[i] = *(const float4*)(Bp + (size_t)(k0 + 32 + 8 * i) * N);
            }
        }
        #pragma unroll
        for (int kc = 0; kc < 4; kc++) {
            const int kb = kc * 8;
            const int c1 = ((kb >> 2) & 7) << 2;        // swizzle for k in [kb, kb+4)
            const int c2 = (((kb >> 2) + 1) & 7) << 2;  // swizzle for k in [kb+4, kb+8)
            unsigned afr[4][4], bfr[4][2];
            #pragma unroll
            for (int tm = 0; tm < 4; tm++) {
                int r0 = wm * 64 + tm * 16 + g;
                afr[tm][0] = As[kb + tig    ][ r0      ^ c1];
                afr[tm][1] = As[kb + tig    ][(r0 + 8) ^ c1];
                afr[tm][2] = As[kb + tig + 4][ r0      ^ c2];
                afr[tm][3] = As[kb + tig + 4][(r0 + 8) ^ c2];
            }
            #pragma unroll
            for (int tn = 0; tn < 4; tn++) {
                int n0 = wn * 32 + tn * 8 + g;
                bfr[tn][0] = Bs[kb + tig    ][n0];
                bfr[tn][1] = Bs[kb + tig + 4][n0];
            }
            #pragma unroll
            for (int tm = 0; tm < 4; tm++)
                #pragma unroll
                for (int tn = 0; tn < 4; tn++)
                    asm volatile(
                        "mma.sync.aligned.m16n8k8.row.col.f32.tf32.tf32.f32 "
                        "{%0,%1,%2,%3}, {%4,%5,%6,%7}, {%8,%9}, {%0,%1,%2,%3};"
                        : "+f"(acc[tm][tn][0]), "+f"(acc[tm][tn][1]),
                          "+f"(acc[tm][tn][2]), "+f"(acc[tm][tn][3])
                        : "r"(afr[tm][0]), "r"(afr[tm][1]),
                          "r"(afr[tm][2]), "r"(afr[tm][3]),
                          "r"(bfr[tn][0]), "r"(bfr[tn][1]));
        }
        __syncthreads();
    }

    #pragma unroll
    for (int tm = 0; tm < 4; tm++) {
        int row0 = bm + wm * 64 + tm * 16 + g;
        #pragma unroll
        for (int tn = 0; tn < 4; tn++) {
            int col = bn + wn * 32 + tn * 8 + tig * 2;
            size_t off0 = (size_t)row0 * N + col;
            size_t off1 = (size_t)(row0 + 8) * N + col;
            float2 r0 = make_float2(acc[tm][tn][0], acc[tm][tn][1]);
            float2 r1 = make_float2(acc[tm][tn][2], acc[tm][tn][3]);
            if (resid) {
                float2 v0 = *(const float2*)(resid + off0);
                float2 v1 = *(const float2*)(resid + off1);
                r0.x += v0.x; r0.y += v0.y;
                r1.x += v1.x; r1.y += v1.y;
            }
            *(float2*)(C + off0) = r0;
            *(float2*)(C + off1) = r1;
        }
    }
}

// Epilogue GEMM: out = y @ wo + x
__global__ void __launch_bounds__(256) tgemm_kernel(
    const float* __restrict__ A, const float* __restrict__ B,
    float* __restrict__ C, const float* __restrict__ resid,
    int K, int N)
{
    tgemm_body(A, B, C, resid, K, N, blockIdx.y * 128, blockIdx.x * 128);
}

// Fused 4-way projection GEMM: same A (x_norm), blockIdx.z selects weight/output.
__global__ void __launch_bounds__(256) tgemm_proj4(
    const float* __restrict__ A,
    const float* __restrict__ B0, const float* __restrict__ B1,
    const float* __restrict__ B2, const float* __restrict__ B3,
    float* __restrict__ C0, float* __restrict__ C1,
    float* __restrict__ C2, float* __restrict__ C3)
{
    const float* B; float* C;
    switch (blockIdx.z) {
        case 0: B = B0; C = C0; break;
        case 1: B = B1; C = C1; break;
        case 2: B = B2; C = C2; break;
        default: B = B3; C = C3; break;
    }
    tgemm_body(A, B, C, nullptr, Dq, Dq, blockIdx.y * 128, blockIdx.x * 128);
}

// ---------------- beta = sigmoid(x@b_proj), decay = exp(-exp(A_log)*softplus(x@a_proj+dt_bias)) ----------------
__global__ void ab_proj_kernel(const float* __restrict__ a_proj,
                               const float* __restrict__ b_proj,
                               const float* __restrict__ A_log,
                               const float* __restrict__ dt_bias)
{
    int row = blockIdx.x;
    int tid = threadIdx.x;  // 256
    __shared__ float xs[Dq];
    ((float4*)xs)[tid] = ((const float4*)(g_xnorm + (size_t)row * Dq))[tid];
    __syncthreads();
    int warp = tid >> 5, lane = tid & 31;
    for (int j = warp; j < 32; j += 8) {
        int h = j & 15;
        bool isB = (j >= 16);
        const float* W = isB ? b_proj : a_proj;
        float s = 0.f;
        for (int k2 = lane; k2 < Dq; k2 += 32) s = fmaf(xs[k2], W[k2 * Hq + h], s);
        #pragma unroll
        for (int o = 16; o; o >>= 1) s += __shfl_xor_sync(0xffffffffu, s, o);
        if (lane == 0) {
            if (isB) {
                g_beta[(size_t)row * Hq + h] = 1.f / (1.f + expf(-s));
            } else {
                float dt = s + dt_bias[h];
                float sp = fmaxf(dt, 0.f) + log1pf(expf(-fabsf(dt)));  // stable softplus
                g_decay[(size_t)row * Hq + h] = expf(-expf(A_log[h]) * sp);
            }
        }
    }
}

// ---------------- depthwise causal conv (K=4) + SiLU (+ optional per-head L2 norm) ----------------
// One launch covers q/k/v: blockIdx.y = 0 (q: conv+silu+l2+*DK^-0.5),
// 1 (k: conv+silu+l2), 2 (v: conv+silu).
__global__ void conv_kernel(const float* __restrict__ qin, const float* __restrict__ kin,
                            const float* __restrict__ vin,
                            const float* __restrict__ qw, const float* __restrict__ kw,
                            const float* __restrict__ vw,
                            float* __restrict__ qout, float* __restrict__ kout,
                            float* __restrict__ vout)
{
    __shared__ float hs[16];
    const int mode = blockIdx.y;   // 0=q, 1=k, 2=v
    const float* in; const float* w; float* out;
    if (mode == 0)      { in = qin; w = qw; out = qout; }
    else if (mode == 1) { in = kin; w = kw; out = kout; }
    else                { in = vin; w = vw; out = vout; }

    int row = blockIdx.x;          // b*T + t
    int t = row & (Tq - 1);
    int c = threadIdx.x;           // 1024 threads = channels
    size_t base = (size_t)row * Dq + c;
    float x3 = in[base];
    float x2 = (t >= 1) ? in[base - 1 * Dq] : 0.f;
    float x1 = (t >= 2) ? in[base - 2 * Dq] : 0.f;
    float x0 = (t >= 3) ? in[base - 3 * Dq] : 0.f;
    float4 wv = ((const float4*)w)[c];     // w[c][0..3]
    // out[t] = sum_k x[t-3+k] * w[3-k]
    float acc = x0 * wv.w + x1 * wv.z + x2 * wv.y + x3 * wv.x;
    float val = acc / (1.f + expf(-acc));  // SiLU
    if (mode == 2) {
        out[base] = val;
    } else {
        if (c < 16) hs[c] = 0.f;
        __syncthreads();
        float sq = val * val;
        #pragma unroll
        for (int o = 16; o; o >>= 1) sq += __shfl_xor_sync(0xffffffffu, sq, o);
        if ((c & 31) == 0) atomicAdd(&hs[c >> 6], sq);
        __syncthreads();
        float n = sqrtf(hs[c >> 6]);
        float r = val / fmaxf(n, 1e-12f);
        if (mode == 0) r *= 0.125f;  // DK^-0.5
        out[base] = r;
    }
}

// ---------------- gated delta-rule scan ----------------
// S[:,dv] evolves independently per dv. Thread = (dv_local, dk-oct): owns
// S[oct*8 .. oct*8+8][dv]; butterfly-shfl over the 8 octs.
// Block = (b, h, dv-quarter): 128 threads (16 dv x 8 oct). Grid = 4*16*4 = 256 blocks.
#define TS 16
__global__ void __launch_bounds__(128) scan_kernel()
{
    int bid = blockIdx.x;
    int bh = bid >> 2, dvq = bid & 3;
    int b = bh >> 4, h = bh & 15;
    int tid = threadIdx.x;
    int oct = tid & 7, dvl = tid >> 3;   // dvl in [0,16)

    __shared__ float sk[TS][64], sq[TS][64], sv[TS][16], sb[TS], sd[TS], so[TS][16];

    float s[8];
    #pragma unroll
    for (int i = 0; i < 8; i++) s[i] = 0.f;

    size_t baseRow = (size_t)b * Tq;
    int hoff = h * 64;

    for (int t0 = 0; t0 < Tq; t0 += TS) {
        for (int m = tid; m < TS * 64; m += 128) {
            int tl = m >> 6, ci = m & 63;
            size_t goff = (baseRow + t0 + tl) * (size_t)Dq + hoff + ci;
            sk[tl][ci] = g_kc[goff];
            sq[tl][ci] = g_qc[goff];
        }
        for (int m = tid; m < TS * 16; m += 128) {
            int tl = m >> 4, ci = m & 15;
            sv[tl][ci] = g_vc[(baseRow + t0 + tl) * (size_t)Dq + hoff + dvq * 16 + ci];
        }
        if (tid < TS) {
            sb[tid] = g_beta [(baseRow + t0 + tid) * Hq + h];
            sd[tid] = g_decay[(baseRow + t0 + tid) * Hq + h];
        }
        __syncthreads();   // A: also separates so writes below from prior-tile so reads

        for (int tl = 0; tl < TS; tl++) {
            float k[8], q[8];
            *(float4*)&k[0] = *(const float4*)&sk[tl][oct * 8];
            *(float4*)&k[4] = *(const float4*)&sk[tl][oct * 8 + 4];
            *(float4*)&q[0] = *(const float4*)&sq[tl][oct * 8];
            *(float4*)&q[4] = *(const float4*)&sq[tl][oct * 8 + 4];
            float v  = sv[tl][dvl];
            float bt = sb[tl];
            float dc = sd[tl];
            // c = k . S_old[:,dv]  (pre-decay)
            float c0 = 0.f, c1 = 0.f;
            #pragma unroll
            for (int i = 0; i < 4; i++) {
                c0 = fmaf(k[i],     s[i],     c0);
                c1 = fmaf(k[i + 4], s[i + 4], c1);
            }
            float c = c0 + c1;
            c += __shfl_xor_sync(0xffffffffu, c, 1);
            c += __shfl_xor_sync(0xffffffffu, c, 2);
            c += __shfl_xor_sync(0xffffffffu, c, 4);
            // err = v - decay*(k.S_old);  g = beta*err
            float g = bt * (v - dc * c);
            // S_new = decay*S_old + g*k ; o = q . S_new
            float o0 = 0.f, o1 = 0.f;
            #pragma unroll
            for (int i = 0; i < 8; i++) s[i] = fmaf(dc, s[i], g * k[i]);
            #pragma unroll
            for (int i = 0; i < 4; i++) {
                o0 = fmaf(q[i],     s[i],     o0);
                o1 = fmaf(q[i + 4], s[i + 4], o1);
            }
            float o = o0 + o1;
            o += __shfl_xor_sync(0xffffffffu, o, 1);
            o += __shfl_xor_sync(0xffffffffu, o, 2);
            o += __shfl_xor_sync(0xffffffffu, o, 4);
            if (oct == 0) so[tl][dvl] = o;
        }
        __syncthreads();   // B: separates compute from store + next-tile reload
        for (int m = tid; m < TS * 16; m += 128) {
            int tl = m >> 4, ci = m & 15;
            g_o[(baseRow + t0 + tl) * (size_t)Dq + hoff + dvq * 16 + ci] = so[tl][ci];
        }
    }
}

// ---------------- output gating: y = rmsnorm_dv(o) * o_scale * silu(gate) ----------------
__global__ void gate_kernel(const float* __restrict__ oscale)
{
    __shared__ float hs[16];
    int row = blockIdx.x;
    int c = threadIdx.x;  // 1024
    size_t off = (size_t)row * Dq + c;
    float ov = g_o[off];
    if (c < 16) hs[c] = 0.f;
    __syncthreads();
    float sq = ov * ov;
    #pragma unroll
    for (int o = 16; o; o >>= 1) sq += __shfl_xor_sync(0xffffffffu, sq, o);
    if ((c & 31) == 0) atomicAdd(&hs[c >> 6], sq);
    __syncthreads();
    float inv = rsqrtf(hs[c >> 6] * (1.f / 64.f) + 1e-5f);
    float gt = g_g[off];
    float si = gt / (1.f + expf(-gt));
    g_y[off] = ov * inv * oscale[c & 63] * si;
}

// ---------------- launch ----------------
extern "C" void kernel_launch(void* const* d_in, const int* in_sizes, int n_in,
                              void* d_out, int out_size)
{
    const float* x          = (const float*)d_in[0];
    const float* norm_scale = (const float*)d_in[1];
    const float* wq         = (const float*)d_in[2];
    const float* w_k        = (const float*)d_in[3];
    const float* w_v        = (const float*)d_in[4];
    const float* q_conv_w   = (const float*)d_in[5];
    const float* k_conv_w   = (const float*)d_in[6];
    const float* v_conv_w   = (const float*)d_in[7];
    const float* a_proj     = (const float*)d_in[8];
    const float* A_log      = (const float*)d_in[9];
    const float* dt_bias    = (const float*)d_in[10];
    const float* b_proj     = (const float*)d_in[11];
    const float* g_proj     = (const float*)d_in[12];
    const float* o_norm     = (const float*)d_in[13];
    const float* wo         = (const float*)d_in[14];
    float* out              = (float*)d_out;

    float *p_xnorm, *p_q, *p_k, *p_v, *p_g, *p_qc, *p_kc, *p_vc, *p_y;
    cudaGetSymbolAddress((void**)&p_xnorm, g_xnorm);
    cudaGetSymbolAddress((void**)&p_q,  g_q);
    cudaGetSymbolAddress((void**)&p_k,  g_k);
    cudaGetSymbolAddress((void**)&p_v,  g_v);
    cudaGetSymbolAddress((void**)&p_g,  g_g);
    cudaGetSymbolAddress((void**)&p_qc, g_qc);
    cudaGetSymbolAddress((void**)&p_kc, g_kc);
    cudaGetSymbolAddress((void**)&p_vc, g_vc);
    cudaGetSymbolAddress((void**)&p_y,  g_y);

    rmsnorm_kernel<<<MT, 256>>>(x, norm_scale);

    dim3 proj_grid(Dq / 128, MT / 128, 4);  // (8, 64, 4)
    tgemm_proj4<<<proj_grid, 256>>>(p_xnorm, wq, w_k, w_v, g_proj,
                                    p_q, p_k, p_v, p_g);

    ab_proj_kernel<<<MT, 256>>>(a_proj, b_proj, A_log, dt_bias);

    dim3 conv_grid(MT, 3);
    conv_kernel<<<conv_grid, 1024>>>(p_q, p_k, p_v,
                                     q_conv_w, k_conv_w, v_conv_w,
                                     p_qc, p_kc, p_vc);

    scan_kernel<<<Bq * Hq * 4, 128>>>();

    gate_kernel<<<MT, 1024>>>(o_norm);

    dim3 gemm_grid(Dq / 128, MT / 128);
    tgemm_kernel<<<gemm_grid, 256>>>(p_y, wo, out, x, Dq, Dq);
}

// round 8
// speedup vs baseline: 1.3472x; 1.3472x over previous
#include <cuda_runtime.h>
#include <math.h>

// Problem constants
#define Bq  4
#define Tq  2048
#define Dq  1024
#define Hq  16
#define DKq 64
#define DVq 64
#define MT  (Bq*Tq)   // 8192 rows

// ---------------- scratch (device globals: allocation-free) ----------------
__device__ float g_xnorm[MT*Dq];
__device__ float g_q[MT*Dq];
__device__ float g_k[MT*Dq];
__device__ float g_v[MT*Dq];
__device__ float g_g[MT*Dq];
__device__ float g_qc[MT*Dq];
__device__ float g_kc[MT*Dq];
__device__ float g_vc[MT*Dq];
__device__ float g_beta[MT*Hq];
__device__ float g_decay[MT*Hq];
__device__ float g_o[MT*Dq];
__device__ float g_y[MT*Dq];
__device__ float g_wt[2*Hq*Dq];   // transposed a_proj / b_proj: [2][16][1024]

// ---------------- RMSNorm over D=1024 ----------------
__global__ void rmsnorm_kernel(const float* __restrict__ x, const float* __restrict__ w) {
    int row = blockIdx.x;
    int tid = threadIdx.x;  // 256 threads, 4 floats each
    const float4* xr = (const float4*)(x + (size_t)row * Dq);
    float4 v = xr[tid];
    float ss = v.x*v.x + v.y*v.y + v.z*v.z + v.w*v.w;
    #pragma unroll
    for (int o = 16; o; o >>= 1) ss += __shfl_xor_sync(0xffffffffu, ss, o);
    __shared__ float red[8];
    __shared__ float s_inv;
    int warp = tid >> 5, lane = tid & 31;
    if (lane == 0) red[warp] = ss;
    __syncthreads();
    if (tid == 0) {
        float t2 = 0.f;
        #pragma unroll
        for (int i = 0; i < 8; i++) t2 += red[i];
        s_inv = rsqrtf(t2 * (1.0f / Dq) + 1e-5f);
    }
    __syncthreads();
    float inv = s_inv;
    float4 wv = ((const float4*)w)[tid];
    float4 o4 = make_float4(v.x*inv*wv.x, v.y*inv*wv.y, v.z*inv*wv.z, v.w*inv*wv.w);
    ((float4*)(g_xnorm + (size_t)row * Dq))[tid] = o4;
}

// ---------------- transpose a_proj/b_proj [1024,16] -> [16,1024] ----------------
__global__ void transpose_ab(const float* __restrict__ a_proj,
                             const float* __restrict__ b_proj) {
    int i = blockIdx.x * 256 + threadIdx.x;   // 0..16383
    int k = i >> 4, h = i & 15;
    g_wt[h * Dq + k]           = a_proj[i];
    g_wt[Hq * Dq + h * Dq + k] = b_proj[i];
}

// ---------------- tf32 tensor-core GEMM 128x128, K-step 32, cp.async 2-stage ----------------
// Raw fp32 bits fed to tf32 mma (HW truncates mantissa; RZ rounding).
#define AS_LD 36           // floats per A row (pad: bank = (4*row+k)%32, conflict-free)
#define BS_LD 136          // floats per B row (pad: bank = (8*k+n)%32, conflict-free)
#define STAGE_A (128*AS_LD)
#define STAGE_B (32*BS_LD)
#define STAGE_ELEMS (STAGE_A + STAGE_B)          // 8960 floats
#define GEMM_SMEM_BYTES (2*STAGE_ELEMS*4)        // 71680 bytes

__device__ __forceinline__ void cp16(float* dst_smem, const float* src) {
    unsigned d = (unsigned)__cvta_generic_to_shared(dst_smem);
    asm volatile("cp.async.cg.shared.global [%0], [%1], 16;\n" :: "r"(d), "l"(src) : "memory");
}
__device__ __forceinline__ void cp_commit() {
    asm volatile("cp.async.commit_group;\n" ::: "memory");
}
__device__ __forceinline__ void cp_wait1() {
    asm volatile("cp.async.wait_group 1;\n" ::: "memory");
}

__device__ __forceinline__ void tgemm_body(
    const float* __restrict__ A, const float* __restrict__ B,
    float* __restrict__ C, const float* __restrict__ resid,
    int K, int N, int bm, int bn, float* smem)
{
    const int tid  = threadIdx.x;
    const int lane = tid & 31;
    const int warp = tid >> 5;
    const int wm = warp & 1, wn = warp >> 1;   // 2 x 4 warp grid, warp tile 64x32
    const int g = lane >> 2, tig = lane & 3;

    float acc[4][4][4];
    #pragma unroll
    for (int tm = 0; tm < 4; tm++)
        #pragma unroll
        for (int tn = 0; tn < 4; tn++)
            #pragma unroll
            for (int r = 0; r < 4; r++) acc[tm][tn][r] = 0.f;

    auto issue = [&](int stage, int k0) {
        float* Sa = smem + stage * STAGE_ELEMS;
        float* Sb = Sa + STAGE_A;
        #pragma unroll
        for (int i = 0; i < 4; i++) {
            int c = tid + 256 * i;
            int row = c >> 3, k4 = (c & 7) * 4;          // A: 128 rows x 8 chunks
            cp16(Sa + row * AS_LD + k4, A + (size_t)(bm + row) * K + k0 + k4);
            int kr = c >> 5, n4 = (c & 31) * 4;          // B: 32 rows x 32 chunks
            cp16(Sb + kr * BS_LD + n4, B + (size_t)(k0 + kr) * N + bn + n4);
        }
    };

    issue(0, 0);  cp_commit();
    issue(1, 32); cp_commit();

    const int NT = K / 32;
    for (int kt = 0; kt < NT; kt++) {
        cp_wait1();
        __syncthreads();
        const float* Sa = smem + (kt & 1) * STAGE_ELEMS;
        const float* Sb = Sa + STAGE_A;
        #pragma unroll
        for (int kc = 0; kc < 4; kc++) {
            const int kb = kc * 8;
            unsigned afr[4][4], bfr[4][2];
            #pragma unroll
            for (int tm = 0; tm < 4; tm++) {
                int r0 = wm * 64 + tm * 16 + g;
                afr[tm][0] = __float_as_uint(Sa[ r0      * AS_LD + kb + tig]);
                afr[tm][1] = __float_as_uint(Sa[(r0 + 8) * AS_LD + kb + tig]);
                afr[tm][2] = __float_as_uint(Sa[ r0      * AS_LD + kb + tig + 4]);
                afr[tm][3] = __float_as_uint(Sa[(r0 + 8) * AS_LD + kb + tig + 4]);
            }
            #pragma unroll
            for (int tn = 0; tn < 4; tn++) {
                int n0 = wn * 32 + tn * 8 + g;
                bfr[tn][0] = __float_as_uint(Sb[(kb + tig)     * BS_LD + n0]);
                bfr[tn][1] = __float_as_uint(Sb[(kb + tig + 4) * BS_LD + n0]);
            }
            #pragma unroll
            for (int tm = 0; tm < 4; tm++)
                #pragma unroll
                for (int tn = 0; tn < 4; tn++)
                    asm volatile(
                        "mma.sync.aligned.m16n8k8.row.col.f32.tf32.tf32.f32 "
                        "{%0,%1,%2,%3}, {%4,%5,%6,%7}, {%8,%9}, {%0,%1,%2,%3};"
                        : "+f"(acc[tm][tn][0]), "+f"(acc[tm][tn][1]),
                          "+f"(acc[tm][tn][2]), "+f"(acc[tm][tn][3])
                        : "r"(afr[tm][0]), "r"(afr[tm][1]),
                          "r"(afr[tm][2]), "r"(afr[tm][3]),
                          "r"(bfr[tn][0]), "r"(bfr[tn][1]));
        }
        __syncthreads();
        if (kt + 2 < NT) issue(kt & 1, (kt + 2) * 32);
        cp_commit();
    }

    #pragma unroll
    for (int tm = 0; tm < 4; tm++) {
        int row0 = bm + wm * 64 + tm * 16 + g;
        #pragma unroll
        for (int tn = 0; tn < 4; tn++) {
            int col = bn + wn * 32 + tn * 8 + tig * 2;
            size_t off0 = (size_t)row0 * N + col;
            size_t off1 = (size_t)(row0 + 8) * N + col;
            float2 r0 = make_float2(acc[tm][tn][0], acc[tm][tn][1]);
            float2 r1 = make_float2(acc[tm][tn][2], acc[tm][tn][3]);
            if (resid) {
                float2 v0 = *(const float2*)(resid + off0);
                float2 v1 = *(const float2*)(resid + off1);
                r0.x += v0.x; r0.y += v0.y;
                r1.x += v1.x; r1.y += v1.y;
            }
            *(float2*)(C + off0) = r0;
            *(float2*)(C + off1) = r1;
        }
    }
}

// Epilogue GEMM: out = y @ wo + x
__global__ void __launch_bounds__(256) tgemm_kernel(
    const float* __restrict__ A, const float* __restrict__ B,
    float* __restrict__ C, const float* __restrict__ resid,
    int K, int N)
{
    extern __shared__ float dynsmem[];
    tgemm_body(A, B, C, resid, K, N, blockIdx.y * 128, blockIdx.x * 128, dynsmem);
}

// Fused 4-way projection GEMM: same A (x_norm), blockIdx.z selects weight/output.
__global__ void __launch_bounds__(256) tgemm_proj4(
    const float* __restrict__ A,
    const float* __restrict__ B0, const float* __restrict__ B1,
    const float* __restrict__ B2, const float* __restrict__ B3,
    float* __restrict__ C0, float* __restrict__ C1,
    float* __restrict__ C2, float* __restrict__ C3)
{
    extern __shared__ float dynsmem[];
    const float* B; float* C;
    switch (blockIdx.z) {
        case 0: B = B0; C = C0; break;
        case 1: B = B1; C = C1; break;
        case 2: B = B2; C = C2; break;
        default: B = B3; C = C3; break;
    }
    tgemm_body(A, B, C, nullptr, Dq, Dq, blockIdx.y * 128, blockIdx.x * 128, dynsmem);
}

// ---------------- beta = sigmoid(x@b_proj), decay = exp(-exp(A_log)*softplus(x@a_proj+dt_bias)) ----------------
// Uses transposed weights g_wt (coalesced float4 reads, L2-resident).
__global__ void ab_proj_kernel(const float* __restrict__ A_log,
                               const float* __restrict__ dt_bias)
{
    int row = blockIdx.x;
    int tid = threadIdx.x;  // 256
    __shared__ float4 xs4[256];
    xs4[tid] = ((const float4*)(g_xnorm + (size_t)row * Dq))[tid];
    __syncthreads();
    int warp = tid >> 5, lane = tid & 31;
    for (int j = warp; j < 32; j += 8) {
        int h = j & 15;
        const float4* W4 = (const float4*)(g_wt + (j >> 4) * (Hq * Dq) + h * Dq);
        float s = 0.f;
        #pragma unroll
        for (int it = 0; it < 8; it++) {
            float4 w  = W4[lane + 32 * it];
            float4 xv = xs4[lane + 32 * it];
            s += xv.x*w.x + xv.y*w.y + xv.z*w.z + xv.w*w.w;
        }
        #pragma unroll
        for (int o = 16; o; o >>= 1) s += __shfl_xor_sync(0xffffffffu, s, o);
        if (lane == 0) {
            if (j >= 16) {
                g_beta[(size_t)row * Hq + h] = 1.f / (1.f + expf(-s));
            } else {
                float dt = s + dt_bias[h];
                float sp = fmaxf(dt, 0.f) + log1pf(expf(-fabsf(dt)));  // stable softplus
                g_decay[(size_t)row * Hq + h] = expf(-expf(A_log[h]) * sp);
            }
        }
    }
}

// ---------------- depthwise causal conv (K=4) + SiLU (+ optional per-head L2 norm) ----------------
// One launch covers q/k/v: blockIdx.y = 0 (q: conv+silu+l2+*DK^-0.5),
// 1 (k: conv+silu+l2), 2 (v: conv+silu).
__global__ void conv_kernel(const float* __restrict__ qin, const float* __restrict__ kin,
                            const float* __restrict__ vin,
                            const float* __restrict__ qw, const float* __restrict__ kw,
                            const float* __restrict__ vw,
                            float* __restrict__ qout, float* __restrict__ kout,
                            float* __restrict__ vout)
{
    __shared__ float hs[16];
    const int mode = blockIdx.y;   // 0=q, 1=k, 2=v
    const float* in; const float* w; float* out;
    if (mode == 0)      { in = qin; w = qw; out = qout; }
    else if (mode == 1) { in = kin; w = kw; out = kout; }
    else                { in = vin; w = vw; out = vout; }

    int row = blockIdx.x;          // b*T + t
    int t = row & (Tq - 1);
    int c = threadIdx.x;           // 1024 threads = channels
    size_t base = (size_t)row * Dq + c;
    float x3 = in[base];
    float x2 = (t >= 1) ? in[base - 1 * Dq] : 0.f;
    float x1 = (t >= 2) ? in[base - 2 * Dq] : 0.f;
    float x0 = (t >= 3) ? in[base - 3 * Dq] : 0.f;
    float4 wv = ((const float4*)w)[c];     // w[c][0..3]
    // out[t] = sum_k x[t-3+k] * w[3-k]
    float acc = x0 * wv.w + x1 * wv.z + x2 * wv.y + x3 * wv.x;
    float val = acc / (1.f + expf(-acc));  // SiLU
    if (mode == 2) {
        out[base] = val;
    } else {
        if (c < 16) hs[c] = 0.f;
        __syncthreads();
        float sq = val * val;
        #pragma unroll
        for (int o = 16; o; o >>= 1) sq += __shfl_xor_sync(0xffffffffu, sq, o);
        if ((c & 31) == 0) atomicAdd(&hs[c >> 6], sq);
        __syncthreads();
        float n = sqrtf(hs[c >> 6]);
        float r = val / fmaxf(n, 1e-12f);
        if (mode == 0) r *= 0.125f;  // DK^-0.5
        out[base] = r;
    }
}

// ---------------- gated delta-rule scan ----------------
// S[:,dv] evolves independently per dv. Thread = (dv_local, dk-oct): owns
// S[oct*8 .. oct*8+8][dv]; butterfly-shfl over the 8 octs.
// Block = (b, h, dv-quarter): 128 threads (16 dv x 8 oct). Grid = 4*16*4 = 256 blocks.
#define TS 16
__global__ void __launch_bounds__(128) scan_kernel()
{
    int bid = blockIdx.x;
    int bh = bid >> 2, dvq = bid & 3;
    int b = bh >> 4, h = bh & 15;
    int tid = threadIdx.x;
    int oct = tid & 7, dvl = tid >> 3;   // dvl in [0,16)

    __shared__ float sk[TS][64], sq[TS][64], sv[TS][16], sb[TS], sd[TS], so[TS][16];

    float s[8];
    #pragma unroll
    for (int i = 0; i < 8; i++) s[i] = 0.f;

    size_t baseRow = (size_t)b * Tq;
    int hoff = h * 64;

    for (int t0 = 0; t0 < Tq; t0 += TS) {
        for (int m = tid; m < TS * 64; m += 128) {
            int tl = m >> 6, ci = m & 63;
            size_t goff = (baseRow + t0 + tl) * (size_t)Dq + hoff + ci;
            sk[tl][ci] = g_kc[goff];
            sq[tl][ci] = g_qc[goff];
        }
        for (int m = tid; m < TS * 16; m += 128) {
            int tl = m >> 4, ci = m & 15;
            sv[tl][ci] = g_vc[(baseRow + t0 + tl) * (size_t)Dq + hoff + dvq * 16 + ci];
        }
        if (tid < TS) {
            sb[tid] = g_beta [(baseRow + t0 + tid) * Hq + h];
            sd[tid] = g_decay[(baseRow + t0 + tid) * Hq + h];
        }
        __syncthreads();   // A: also separates so writes below from prior-tile so reads

        for (int tl = 0; tl < TS; tl++) {
            float k[8], q[8];
            *(float4*)&k[0] = *(const float4*)&sk[tl][oct * 8];
            *(float4*)&k[4] = *(const float4*)&sk[tl][oct * 8 + 4];
            *(float4*)&q[0] = *(const float4*)&sq[tl][oct * 8];
            *(float4*)&q[4] = *(const float4*)&sq[tl][oct * 8 + 4];
            float v  = sv[tl][dvl];
            float bt = sb[tl];
            float dc = sd[tl];
            // c = k . S_old[:,dv]  (pre-decay)
            float c0 = 0.f, c1 = 0.f;
            #pragma unroll
            for (int i = 0; i < 4; i++) {
                c0 = fmaf(k[i],     s[i],     c0);
                c1 = fmaf(k[i + 4], s[i + 4], c1);
            }
            float c = c0 + c1;
            c += __shfl_xor_sync(0xffffffffu, c, 1);
            c += __shfl_xor_sync(0xffffffffu, c, 2);
            c += __shfl_xor_sync(0xffffffffu, c, 4);
            // err = v - decay*(k.S_old);  g = beta*err
            float g = bt * (v - dc * c);
            // S_new = decay*S_old + g*k ; o = q . S_new
            float o0 = 0.f, o1 = 0.f;
            #pragma unroll
            for (int i = 0; i < 8; i++) s[i] = fmaf(dc, s[i], g * k[i]);
            #pragma unroll
            for (int i = 0; i < 4; i++) {
                o0 = fmaf(q[i],     s[i],     o0);
                o1 = fmaf(q[i + 4], s[i + 4], o1);
            }
            float o = o0 + o1;
            o += __shfl_xor_sync(0xffffffffu, o, 1);
            o += __shfl_xor_sync(0xffffffffu, o, 2);
            o += __shfl_xor_sync(0xffffffffu, o, 4);
            if (oct == 0) so[tl][dvl] = o;
        }
        __syncthreads();   // B: separates compute from store + next-tile reload
        for (int m = tid; m < TS * 16; m += 128) {
            int tl = m >> 4, ci = m & 15;
            g_o[(baseRow + t0 + tl) * (size_t)Dq + hoff + dvq * 16 + ci] = so[tl][ci];
        }
    }
}

// ---------------- output gating: y = rmsnorm_dv(o) * o_scale * silu(gate) ----------------
__global__ void gate_kernel(const float* __restrict__ oscale)
{
    __shared__ float hs[16];
    int row = blockIdx.x;
    int c = threadIdx.x;  // 1024
    size_t off = (size_t)row * Dq + c;
    float ov = g_o[off];
    if (c < 16) hs[c] = 0.f;
    __syncthreads();
    float sq = ov * ov;
    #pragma unroll
    for (int o = 16; o; o >>= 1) sq += __shfl_xor_sync(0xffffffffu, sq, o);
    if ((c & 31) == 0) atomicAdd(&hs[c >> 6], sq);
    __syncthreads();
    float inv = rsqrtf(hs[c >> 6] * (1.f / 64.f) + 1e-5f);
    float gt = g_g[off];
    float si = gt / (1.f + expf(-gt));
    g_y[off] = ov * inv * oscale[c & 63] * si;
}

// ---------------- launch ----------------
extern "C" void kernel_launch(void* const* d_in, const int* in_sizes, int n_in,
                              void* d_out, int out_size)
{
    const float* x          = (const float*)d_in[0];
    const float* norm_scale = (const float*)d_in[1];
    const float* wq         = (const float*)d_in[2];
    const float* w_k        = (const float*)d_in[3];
    const float* w_v        = (const float*)d_in[4];
    const float* q_conv_w   = (const float*)d_in[5];
    const float* k_conv_w   = (const float*)d_in[6];
    const float* v_conv_w   = (const float*)d_in[7];
    const float* a_proj     = (const float*)d_in[8];
    const float* A_log      = (const float*)d_in[9];
    const float* dt_bias    = (const float*)d_in[10];
    const float* b_proj     = (const float*)d_in[11];
    const float* g_proj     = (const float*)d_in[12];
    const float* o_norm     = (const float*)d_in[13];
    const float* wo         = (const float*)d_in[14];
    float* out              = (float*)d_out;

    float *p_xnorm, *p_q, *p_k, *p_v, *p_g, *p_qc, *p_kc, *p_vc, *p_y;
    cudaGetSymbolAddress((void**)&p_xnorm, g_xnorm);
    cudaGetSymbolAddress((void**)&p_q,  g_q);
    cudaGetSymbolAddress((void**)&p_k,  g_k);
    cudaGetSymbolAddress((void**)&p_v,  g_v);
    cudaGetSymbolAddress((void**)&p_g,  g_g);
    cudaGetSymbolAddress((void**)&p_qc, g_qc);
    cudaGetSymbolAddress((void**)&p_kc, g_kc);
    cudaGetSymbolAddress((void**)&p_vc, g_vc);
    cudaGetSymbolAddress((void**)&p_y,  g_y);

    cudaFuncSetAttribute(tgemm_proj4, cudaFuncAttributeMaxDynamicSharedMemorySize, GEMM_SMEM_BYTES);
    cudaFuncSetAttribute(tgemm_kernel, cudaFuncAttributeMaxDynamicSharedMemorySize, GEMM_SMEM_BYTES);

    transpose_ab<<<64, 256>>>(a_proj, b_proj);
    rmsnorm_kernel<<<MT, 256>>>(x, norm_scale);

    dim3 proj_grid(Dq / 128, MT / 128, 4);  // (8, 64, 4)
    tgemm_proj4<<<proj_grid, 256, GEMM_SMEM_BYTES>>>(p_xnorm, wq, w_k, w_v, g_proj,
                                                     p_q, p_k, p_v, p_g);

    ab_proj_kernel<<<MT, 256>>>(A_log, dt_bias);

    dim3 conv_grid(MT, 3);
    conv_kernel<<<conv_grid, 1024>>>(p_q, p_k, p_v,
                                     q_conv_w, k_conv_w, v_conv_w,
                                     p_qc, p_kc, p_vc);

    scan_kernel<<<Bq * Hq * 4, 128>>>();

    gate_kernel<<<MT, 1024>>>(o_norm);

    dim3 gemm_grid(Dq / 128, MT / 128);
    tgemm_kernel<<<gemm_grid, 256, GEMM_SMEM_BYTES>>>(p_y, wo, out, x, Dq, Dq);
}

// round 9
// speedup vs baseline: 1.3733x; 1.0194x over previous
#include <cuda_runtime.h>
#include <math.h>

// Problem constants
#define Bq  4
#define Tq  2048
#define Dq  1024
#define Hq  16
#define DKq 64
#define DVq 64
#define MT  (Bq*Tq)   // 8192 rows

// ---------------- scratch (device globals: allocation-free) ----------------
__device__ float g_xnorm[MT*Dq];
__device__ float g_q[MT*Dq];
__device__ float g_k[MT*Dq];
__device__ float g_v[MT*Dq];
__device__ float g_g[MT*Dq];
__device__ float g_qc[MT*Dq];
__device__ float g_kc[MT*Dq];
__device__ float g_vc[MT*Dq];
__device__ float g_beta[MT*Hq];
__device__ float g_decay[MT*Hq];
__device__ float g_o[MT*Dq];
__device__ float g_y[MT*Dq];
__device__ float g_wt[2*Hq*Dq];   // transposed a_proj / b_proj: [2][16][1024]

// ---------------- RMSNorm over D=1024 ----------------
__global__ void rmsnorm_kernel(const float* __restrict__ x, const float* __restrict__ w) {
    int row = blockIdx.x;
    int tid = threadIdx.x;  // 256 threads, 4 floats each
    const float4* xr = (const float4*)(x + (size_t)row * Dq);
    float4 v = xr[tid];
    float ss = v.x*v.x + v.y*v.y + v.z*v.z + v.w*v.w;
    #pragma unroll
    for (int o = 16; o; o >>= 1) ss += __shfl_xor_sync(0xffffffffu, ss, o);
    __shared__ float red[8];
    __shared__ float s_inv;
    int warp = tid >> 5, lane = tid & 31;
    if (lane == 0) red[warp] = ss;
    __syncthreads();
    if (tid == 0) {
        float t2 = 0.f;
        #pragma unroll
        for (int i = 0; i < 8; i++) t2 += red[i];
        s_inv = rsqrtf(t2 * (1.0f / Dq) + 1e-5f);
    }
    __syncthreads();
    float inv = s_inv;
    float4 wv = ((const float4*)w)[tid];
    float4 o4 = make_float4(v.x*inv*wv.x, v.y*inv*wv.y, v.z*inv*wv.z, v.w*inv*wv.w);
    ((float4*)(g_xnorm + (size_t)row * Dq))[tid] = o4;
}

// ---------------- transpose a_proj/b_proj [1024,16] -> [16,1024] ----------------
__global__ void transpose_ab(const float* __restrict__ a_proj,
                             const float* __restrict__ b_proj) {
    int i = blockIdx.x * 256 + threadIdx.x;   // 0..16383
    int k = i >> 4, h = i & 15;
    g_wt[h * Dq + k]           = a_proj[i];
    g_wt[Hq * Dq + h * Dq + k] = b_proj[i];
}

// ---------------- tf32 tensor-core GEMM 128x128, K-step 32, cp.async 2-stage ----------------
// 512 threads, 16 warps in 4x4 grid, warp tile 32x32. Raw fp32 bits -> tf32 mma.
#define AS_LD 36           // floats per A row (pad: conflict-free stores+loads)
#define BS_LD 136          // floats per B row
#define STAGE_A (128*AS_LD)
#define STAGE_B (32*BS_LD)
#define STAGE_ELEMS (STAGE_A + STAGE_B)          // 8960 floats
#define GEMM_SMEM_BYTES (2*STAGE_ELEMS*4)        // 71680 bytes

__device__ __forceinline__ void cp16(float* dst_smem, const float* src) {
    unsigned d = (unsigned)__cvta_generic_to_shared(dst_smem);
    asm volatile("cp.async.cg.shared.global [%0], [%1], 16;\n" :: "r"(d), "l"(src) : "memory");
}
__device__ __forceinline__ void cp_commit() {
    asm volatile("cp.async.commit_group;\n" ::: "memory");
}
__device__ __forceinline__ void cp_wait1() {
    asm volatile("cp.async.wait_group 1;\n" ::: "memory");
}

__device__ __forceinline__ void tgemm_body(
    const float* __restrict__ A, const float* __restrict__ B,
    float* __restrict__ C, const float* __restrict__ resid,
    int K, int N, int bm, int bn, float* smem)
{
    const int tid  = threadIdx.x;      // 0..511
    const int lane = tid & 31;
    const int warp = tid >> 5;         // 0..15
    const int wm = warp & 3, wn = warp >> 2;   // 4 x 4 warp grid, warp tile 32x32
    const int g = lane >> 2, tig = lane & 3;

    float acc[2][4][4];
    #pragma unroll
    for (int tm = 0; tm < 2; tm++)
        #pragma unroll
        for (int tn = 0; tn < 4; tn++)
            #pragma unroll
            for (int r = 0; r < 4; r++) acc[tm][tn][r] = 0.f;

    auto issue = [&](int stage, int k0) {
        float* Sa = smem + stage * STAGE_ELEMS;
        float* Sb = Sa + STAGE_A;
        #pragma unroll
        for (int i = 0; i < 2; i++) {
            int c = tid + 512 * i;
            int row = c >> 3, k4 = (c & 7) * 4;          // A: 128 rows x 8 chunks
            cp16(Sa + row * AS_LD + k4, A + (size_t)(bm + row) * K + k0 + k4);
            int kr = c >> 5, n4 = (c & 31) * 4;          // B: 32 rows x 32 chunks
            cp16(Sb + kr * BS_LD + n4, B + (size_t)(k0 + kr) * N + bn + n4);
        }
    };

    issue(0, 0);  cp_commit();
    issue(1, 32); cp_commit();

    const int NT = K / 32;
    for (int kt = 0; kt < NT; kt++) {
        cp_wait1();
        __syncthreads();
        const float* Sa = smem + (kt & 1) * STAGE_ELEMS;
        const float* Sb = Sa + STAGE_A;
        #pragma unroll
        for (int kc = 0; kc < 4; kc++) {
            const int kb = kc * 8;
            unsigned afr[2][4], bfr[4][2];
            #pragma unroll
            for (int tm = 0; tm < 2; tm++) {
                int r0 = wm * 32 + tm * 16 + g;
                afr[tm][0] = __float_as_uint(Sa[ r0      * AS_LD + kb + tig]);
                afr[tm][1] = __float_as_uint(Sa[(r0 + 8) * AS_LD + kb + tig]);
                afr[tm][2] = __float_as_uint(Sa[ r0      * AS_LD + kb + tig + 4]);
                afr[tm][3] = __float_as_uint(Sa[(r0 + 8) * AS_LD + kb + tig + 4]);
            }
            #pragma unroll
            for (int tn = 0; tn < 4; tn++) {
                int n0 = wn * 32 + tn * 8 + g;
                bfr[tn][0] = __float_as_uint(Sb[(kb + tig)     * BS_LD + n0]);
                bfr[tn][1] = __float_as_uint(Sb[(kb + tig + 4) * BS_LD + n0]);
            }
            #pragma unroll
            for (int tm = 0; tm < 2; tm++)
                #pragma unroll
                for (int tn = 0; tn < 4; tn++)
                    asm volatile(
                        "mma.sync.aligned.m16n8k8.row.col.f32.tf32.tf32.f32 "
                        "{%0,%1,%2,%3}, {%4,%5,%6,%7}, {%8,%9}, {%0,%1,%2,%3};"
                        : "+f"(acc[tm][tn][0]), "+f"(acc[tm][tn][1]),
                          "+f"(acc[tm][tn][2]), "+f"(acc[tm][tn][3])
                        : "r"(afr[tm][0]), "r"(afr[tm][1]),
                          "r"(afr[tm][2]), "r"(afr[tm][3]),
                          "r"(bfr[tn][0]), "r"(bfr[tn][1]));
        }
        __syncthreads();
        if (kt + 2 < NT) issue(kt & 1, (kt + 2) * 32);
        cp_commit();
    }

    #pragma unroll
    for (int tm = 0; tm < 2; tm++) {
        int row0 = bm + wm * 32 + tm * 16 + g;
        #pragma unroll
        for (int tn = 0; tn < 4; tn++) {
            int col = bn + wn * 32 + tn * 8 + tig * 2;
            size_t off0 = (size_t)row0 * N + col;
            size_t off1 = (size_t)(row0 + 8) * N + col;
            float2 r0 = make_float2(acc[tm][tn][0], acc[tm][tn][1]);
            float2 r1 = make_float2(acc[tm][tn][2], acc[tm][tn][3]);
            if (resid) {
                float2 v0 = *(const float2*)(resid + off0);
                float2 v1 = *(const float2*)(resid + off1);
                r0.x += v0.x; r0.y += v0.y;
                r1.x += v1.x; r1.y += v1.y;
            }
            *(float2*)(C + off0) = r0;
            *(float2*)(C + off1) = r1;
        }
    }
}

// Epilogue GEMM: out = y @ wo + x
__global__ void __launch_bounds__(512) tgemm_kernel(
    const float* __restrict__ A, const float* __restrict__ B,
    float* __restrict__ C, const float* __restrict__ resid,
    int K, int N)
{
    extern __shared__ float dynsmem[];
    tgemm_body(A, B, C, resid, K, N, blockIdx.y * 128, blockIdx.x * 128, dynsmem);
}

// Fused 4-way projection GEMM: same A (x_norm), blockIdx.z selects weight/output.
__global__ void __launch_bounds__(512) tgemm_proj4(
    const float* __restrict__ A,
    const float* __restrict__ B0, const float* __restrict__ B1,
    const float* __restrict__ B2, const float* __restrict__ B3,
    float* __restrict__ C0, float* __restrict__ C1,
    float* __restrict__ C2, float* __restrict__ C3)
{
    extern __shared__ float dynsmem[];
    const float* B; float* C;
    switch (blockIdx.z) {
        case 0: B = B0; C = C0; break;
        case 1: B = B1; C = C1; break;
        case 2: B = B2; C = C2; break;
        default: B = B3; C = C3; break;
    }
    tgemm_body(A, B, C, nullptr, Dq, Dq, blockIdx.y * 128, blockIdx.x * 128, dynsmem);
}

// ---------------- beta/decay projections: 8 rows per block ----------------
#define ABR 8
__global__ void __launch_bounds__(256) ab_proj_kernel(const float* __restrict__ A_log,
                                                      const float* __restrict__ dt_bias)
{
    int row0 = blockIdx.x * ABR;
    int tid = threadIdx.x;  // 256
    __shared__ float4 xs4[ABR * 256];
    #pragma unroll
    for (int i = 0; i < ABR; i++)
        xs4[i * 256 + tid] = ((const float4*)(g_xnorm + (size_t)(row0 + i) * Dq))[tid];
    __syncthreads();
    int warp = tid >> 5, lane = tid & 31;
    for (int task = warp; task < ABR * 32; task += 8) {
        int r = task >> 5, j = task & 31;
        int h = j & 15;
        const float4* W4 = (const float4*)(g_wt + (j >> 4) * (Hq * Dq) + h * Dq);
        const float4* X4 = xs4 + r * 256;
        float s = 0.f;
        #pragma unroll
        for (int it = 0; it < 8; it++) {
            float4 w  = W4[lane + 32 * it];
            float4 xv = X4[lane + 32 * it];
            s += xv.x*w.x + xv.y*w.y + xv.z*w.z + xv.w*w.w;
        }
        #pragma unroll
        for (int o = 16; o; o >>= 1) s += __shfl_xor_sync(0xffffffffu, s, o);
        if (lane == 0) {
            size_t orow = (size_t)(row0 + r) * Hq + h;
            if (j >= 16) {
                g_beta[orow] = 1.f / (1.f + expf(-s));
            } else {
                float dt = s + dt_bias[h];
                float sp = fmaxf(dt, 0.f) + log1pf(expf(-fabsf(dt)));  // stable softplus
                g_decay[orow] = expf(-expf(A_log[h]) * sp);
            }
        }
    }
}

// ---------------- depthwise causal conv (K=4) + SiLU (+ optional per-head L2 norm) ----------------
__global__ void conv_kernel(const float* __restrict__ qin, const float* __restrict__ kin,
                            const float* __restrict__ vin,
                            const float* __restrict__ qw, const float* __restrict__ kw,
                            const float* __restrict__ vw,
                            float* __restrict__ qout, float* __restrict__ kout,
                            float* __restrict__ vout)
{
    __shared__ float hs[16];
    const int mode = blockIdx.y;   // 0=q, 1=k, 2=v
    const float* in; const float* w; float* out;
    if (mode == 0)      { in = qin; w = qw; out = qout; }
    else if (mode == 1) { in = kin; w = kw; out = kout; }
    else                { in = vin; w = vw; out = vout; }

    int row = blockIdx.x;          // b*T + t
    int t = row & (Tq - 1);
    int c = threadIdx.x;           // 1024 threads = channels
    size_t base = (size_t)row * Dq + c;
    float x3 = in[base];
    float x2 = (t >= 1) ? in[base - 1 * Dq] : 0.f;
    float x1 = (t >= 2) ? in[base - 2 * Dq] : 0.f;
    float x0 = (t >= 3) ? in[base - 3 * Dq] : 0.f;
    float4 wv = ((const float4*)w)[c];     // w[c][0..3]
    float acc = x0 * wv.w + x1 * wv.z + x2 * wv.y + x3 * wv.x;
    float val = acc / (1.f + expf(-acc));  // SiLU
    if (mode == 2) {
        out[base] = val;
    } else {
        if (c < 16) hs[c] = 0.f;
        __syncthreads();
        float sq = val * val;
        #pragma unroll
        for (int o = 16; o; o >>= 1) sq += __shfl_xor_sync(0xffffffffu, sq, o);
        if ((c & 31) == 0) atomicAdd(&hs[c >> 6], sq);
        __syncthreads();
        float n = sqrtf(hs[c >> 6]);
        float r = val / fmaxf(n, 1e-12f);
        if (mode == 0) r *= 0.125f;  // DK^-0.5
        out[base] = r;
    }
}

// ---------------- gated delta-rule scan ----------------
// Recurrence chain keeps only the c-reduction shfls; output o = q.S is
// accumulated as per-oct partials in smem and reduced at tile dump.
#define TS 16
__global__ void __launch_bounds__(128) scan_kernel()
{
    int bid = blockIdx.x;
    int bh = bid >> 2, dvq = bid & 3;
    int b = bh >> 4, h = bh & 15;
    int tid = threadIdx.x;
    int oct = tid & 7, dvl = tid >> 3;   // dvl in [0,16)

    __shared__ float sk[TS][64], sq[TS][64], sv[TS][16], sb[TS], sd[TS];
    __shared__ float sop[TS][16][8];     // per-oct partial outputs

    float s[8];
    #pragma unroll
    for (int i = 0; i < 8; i++) s[i] = 0.f;

    size_t baseRow = (size_t)b * Tq;
    int hoff = h * 64;

    for (int t0 = 0; t0 < Tq; t0 += TS) {
        for (int m = tid; m < TS * 64; m += 128) {
            int tl = m >> 6, ci = m & 63;
            size_t goff = (baseRow + t0 + tl) * (size_t)Dq + hoff + ci;
            sk[tl][ci] = g_kc[goff];
            sq[tl][ci] = g_qc[goff];
        }
        for (int m = tid; m < TS * 16; m += 128) {
            int tl = m >> 4, ci = m & 15;
            sv[tl][ci] = g_vc[(baseRow + t0 + tl) * (size_t)Dq + hoff + dvq * 16 + ci];
        }
        if (tid < TS) {
            sb[tid] = g_beta [(baseRow + t0 + tid) * Hq + h];
            sd[tid] = g_decay[(baseRow + t0 + tid) * Hq + h];
        }
        __syncthreads();   // A

        for (int tl = 0; tl < TS; tl++) {
            float k[8], q[8];
            *(float4*)&k[0] = *(const float4*)&sk[tl][oct * 8];
            *(float4*)&k[4] = *(const float4*)&sk[tl][oct * 8 + 4];
            *(float4*)&q[0] = *(const float4*)&sq[tl][oct * 8];
            *(float4*)&q[4] = *(const float4*)&sq[tl][oct * 8 + 4];
            float v  = sv[tl][dvl];
            float bt = sb[tl];
            float dc = sd[tl];
            // c = k . S_old[:,dv]  (pre-decay)
            float c0 = 0.f, c1 = 0.f;
            #pragma unroll
            for (int i = 0; i < 4; i++) {
                c0 = fmaf(k[i],     s[i],     c0);
                c1 = fmaf(k[i + 4], s[i + 4], c1);
            }
            float c = c0 + c1;
            c += __shfl_xor_sync(0xffffffffu, c, 1);
            c += __shfl_xor_sync(0xffffffffu, c, 2);
            c += __shfl_xor_sync(0xffffffffu, c, 4);
            // g = beta * (v - decay*(k.S_old));  S_new = decay*S_old + g*k
            float g = bt * (v - dc * c);
            float o0 = 0.f, o1 = 0.f;
            #pragma unroll
            for (int i = 0; i < 8; i++) s[i] = fmaf(dc, s[i], g * k[i]);
            #pragma unroll
            for (int i = 0; i < 4; i++) {
                o0 = fmaf(q[i],     s[i],     o0);
                o1 = fmaf(q[i + 4], s[i + 4], o1);
            }
            sop[tl][dvl][oct] = o0 + o1;   // partial; reduced at dump
        }
        __syncthreads();   // B
        for (int m = tid; m < TS * 16; m += 128) {
            int tl = m >> 4, ci = m & 15;
            float4 p0 = *(const float4*)&sop[tl][ci][0];
            float4 p1 = *(const float4*)&sop[tl][ci][4];
            float o = (p0.x + p0.y + p0.z + p0.w) + (p1.x + p1.y + p1.z + p1.w);
            g_o[(baseRow + t0 + tl) * (size_t)Dq + hoff + dvq * 16 + ci] = o;
        }
    }
}

// ---------------- output gating: y = rmsnorm_dv(o) * o_scale * silu(gate) ----------------
__global__ void gate_kernel(const float* __restrict__ oscale)
{
    __shared__ float hs[16];
    int row = blockIdx.x;
    int c = threadIdx.x;  // 1024
    size_t off = (size_t)row * Dq + c;
    float ov = g_o[off];
    if (c < 16) hs[c] = 0.f;
    __syncthreads();
    float sq = ov * ov;
    #pragma unroll
    for (int o = 16; o; o >>= 1) sq += __shfl_xor_sync(0xffffffffu, sq, o);
    if ((c & 31) == 0) atomicAdd(&hs[c >> 6], sq);
    __syncthreads();
    float inv = rsqrtf(hs[c >> 6] * (1.f / 64.f) + 1e-5f);
    float gt = g_g[off];
    float si = gt / (1.f + expf(-gt));
    g_y[off] = ov * inv * oscale[c & 63] * si;
}

// ---------------- launch ----------------
extern "C" void kernel_launch(void* const* d_in, const int* in_sizes, int n_in,
                              void* d_out, int out_size)
{
    const float* x          = (const float*)d_in[0];
    const float* norm_scale = (const float*)d_in[1];
    const float* wq         = (const float*)d_in[2];
    const float* w_k        = (const float*)d_in[3];
    const float* w_v        = (const float*)d_in[4];
    const float* q_conv_w   = (const float*)d_in[5];
    const float* k_conv_w   = (const float*)d_in[6];
    const float* v_conv_w   = (const float*)d_in[7];
    const float* a_proj     = (const float*)d_in[8];
    const float* A_log      = (const float*)d_in[9];
    const float* dt_bias    = (const float*)d_in[10];
    const float* b_proj     = (const float*)d_in[11];
    const float* g_proj     = (const float*)d_in[12];
    const float* o_norm     = (const float*)d_in[13];
    const float* wo         = (const float*)d_in[14];
    float* out              = (float*)d_out;

    float *p_xnorm, *p_q, *p_k, *p_v, *p_g, *p_qc, *p_kc, *p_vc, *p_y;
    cudaGetSymbolAddress((void**)&p_xnorm, g_xnorm);
    cudaGetSymbolAddress((void**)&p_q,  g_q);
    cudaGetSymbolAddress((void**)&p_k,  g_k);
    cudaGetSymbolAddress((void**)&p_v,  g_v);
    cudaGetSymbolAddress((void**)&p_g,  g_g);
    cudaGetSymbolAddress((void**)&p_qc, g_qc);
    cudaGetSymbolAddress((void**)&p_kc, g_kc);
    cudaGetSymbolAddress((void**)&p_vc, g_vc);
    cudaGetSymbolAddress((void**)&p_y,  g_y);

    cudaFuncSetAttribute(tgemm_proj4, cudaFuncAttributeMaxDynamicSharedMemorySize, GEMM_SMEM_BYTES);
    cudaFuncSetAttribute(tgemm_kernel, cudaFuncAttributeMaxDynamicSharedMemorySize, GEMM_SMEM_BYTES);

    transpose_ab<<<64, 256>>>(a_proj, b_proj);
    rmsnorm_kernel<<<MT, 256>>>(x, norm_scale);

    dim3 proj_grid(Dq / 128, MT / 128, 4);  // (8, 64, 4)
    tgemm_proj4<<<proj_grid, 512, GEMM_SMEM_BYTES>>>(p_xnorm, wq, w_k, w_v, g_proj,
                                                     p_q, p_k, p_v, p_g);

    ab_proj_kernel<<<MT / ABR, 256>>>(A_log, dt_bias);

    dim3 conv_grid(MT, 3);
    conv_kernel<<<conv_grid, 1024>>>(p_q, p_k, p_v,
                                     q_conv_w, k_conv_w, v_conv_w,
                                     p_qc, p_kc, p_vc);

    scan_kernel<<<Bq * Hq * 4, 128>>>();

    gate_kernel<<<MT, 1024>>>(o_norm);

    dim3 gemm_grid(Dq / 128, MT / 128);
    tgemm_kernel<<<gemm_grid, 512, GEMM_SMEM_BYTES>>>(p_y, wo, out, x, Dq, Dq);
}

// round 17
// speedup vs baseline: 1.4530x; 1.0581x over previous
#include <cuda_runtime.h>
#include <math.h>

// Problem constants
#define Bq  4
#define Tq  2048
#define Dq  1024
#define Hq  16
#define DKq 64
#define DVq 64
#define MT  (Bq*Tq)   // 8192 rows

// ---------------- scratch (device globals: allocation-free) ----------------
__device__ float g_xnorm[MT*Dq];
__device__ float g_q[MT*Dq];
__device__ float g_k[MT*Dq];
__device__ float g_v[MT*Dq];
__device__ float g_g[MT*Dq];
__device__ float g_qc[MT*Dq];
__device__ float g_kc[MT*Dq];
__device__ float g_vc[MT*Dq];
__device__ float g_beta[MT*Hq];
__device__ float g_decay[MT*Hq];
__device__ float g_o[MT*Dq];
__device__ float g_y[MT*Dq];
__device__ float g_wt[2*Hq*Dq];   // transposed a_proj / b_proj: [2][16][1024]

// ---------------- RMSNorm over D=1024 ----------------
__global__ void rmsnorm_kernel(const float* __restrict__ x, const float* __restrict__ w) {
    int row = blockIdx.x;
    int tid = threadIdx.x;  // 256 threads, 4 floats each
    const float4* xr = (const float4*)(x + (size_t)row * Dq);
    float4 v = xr[tid];
    float ss = v.x*v.x + v.y*v.y + v.z*v.z + v.w*v.w;
    #pragma unroll
    for (int o = 16; o; o >>= 1) ss += __shfl_xor_sync(0xffffffffu, ss, o);
    __shared__ float red[8];
    __shared__ float s_inv;
    int warp = tid >> 5, lane = tid & 31;
    if (lane == 0) red[warp] = ss;
    __syncthreads();
    if (tid == 0) {
        float t2 = 0.f;
        #pragma unroll
        for (int i = 0; i < 8; i++) t2 += red[i];
        s_inv = rsqrtf(t2 * (1.0f / Dq) + 1e-5f);
    }
    __syncthreads();
    float inv = s_inv;
    float4 wv = ((const float4*)w)[tid];
    float4 o4 = make_float4(v.x*inv*wv.x, v.y*inv*wv.y, v.z*inv*wv.z, v.w*inv*wv.w);
    ((float4*)(g_xnorm + (size_t)row * Dq))[tid] = o4;
}

// ---------------- transpose a_proj/b_proj [1024,16] -> [16,1024] ----------------
__global__ void transpose_ab(const float* __restrict__ a_proj,
                             const float* __restrict__ b_proj) {
    int i = blockIdx.x * 256 + threadIdx.x;   // 0..16383
    int k = i >> 4, h = i & 15;
    g_wt[h * Dq + k]           = a_proj[i];
    g_wt[Hq * Dq + h * Dq + k] = b_proj[i];
}

// ---------------- tf32 tensor-core GEMM: CTA 128x256, 8 warps of 64x64 ----------------
// 2-stage cp.async pipeline; raw fp32 bits -> tf32 mma (RZ truncation).
#define AS_LD 36
#define BSN   256
#define BS_LD 264
#define STAGE_A (128*AS_LD)                  // 4608 floats
#define STAGE_B (32*BS_LD)                   // 8448 floats
#define STAGE_ELEMS (STAGE_A + STAGE_B)      // 13056 floats
#define GEMM_SMEM_BYTES (2*STAGE_ELEMS*4)    // 104448 bytes

__device__ __forceinline__ void cp16(float* dst_smem, const float* src) {
    unsigned d = (unsigned)__cvta_generic_to_shared(dst_smem);
    asm volatile("cp.async.cg.shared.global [%0], [%1], 16;\n" :: "r"(d), "l"(src) : "memory");
}
__device__ __forceinline__ void cp_commit() {
    asm volatile("cp.async.commit_group;\n" ::: "memory");
}
__device__ __forceinline__ void cp_wait1() {
    asm volatile("cp.async.wait_group 1;\n" ::: "memory");
}

__device__ __forceinline__ void tgemm_body(
    const float* __restrict__ A, const float* __restrict__ B,
    float* __restrict__ C, const float* __restrict__ resid,
    int K, int N, int bm, int bn, float* smem)
{
    const int tid  = threadIdx.x;      // 0..255
    const int lane = tid & 31;
    const int warp = tid >> 5;         // 0..7
    const int wm = warp & 1, wn = warp >> 1;   // 2 x 4 warp grid, warp tile 64x64
    const int g = lane >> 2, tig = lane & 3;

    float acc[4][8][4];
    #pragma unroll
    for (int tm = 0; tm < 4; tm++)
        #pragma unroll
        for (int tn = 0; tn < 8; tn++)
            #pragma unroll
            for (int r = 0; r < 4; r++) acc[tm][tn][r] = 0.f;

    auto issue = [&](int stage, int k0) {
        float* Sa = smem + stage * STAGE_ELEMS;
        float* Sb = Sa + STAGE_A;
        #pragma unroll
        for (int i = 0; i < 4; i++) {              // A: 128 rows x 8 chunks = 1024
            int c = tid + 256 * i;
            int row = c >> 3, k4 = (c & 7) * 4;
            cp16(Sa + row * AS_LD + k4, A + (size_t)(bm + row) * K + k0 + k4);
        }
        #pragma unroll
        for (int i = 0; i < 8; i++) {              // B: 32 rows x 64 chunks = 2048
            int c = tid + 256 * i;
            int kr = c >> 6, n4 = (c & 63) * 4;
            cp16(Sb + kr * BS_LD + n4, B + (size_t)(k0 + kr) * N + bn + n4);
        }
    };

    issue(0, 0);  cp_commit();
    issue(1, 32); cp_commit();

    const int NT = K / 32;
    for (int kt = 0; kt < NT; kt++) {
        cp_wait1();
        __syncthreads();
        const float* Sa = smem + (kt & 1) * STAGE_ELEMS;
        const float* Sb = Sa + STAGE_A;
        #pragma unroll
        for (int kc = 0; kc < 4; kc++) {
            const int kb = kc * 8;
            unsigned afr[4][4], bfr[8][2];
            #pragma unroll
            for (int tm = 0; tm < 4; tm++) {
                int r0 = wm * 64 + tm * 16 + g;
                afr[tm][0] = __float_as_uint(Sa[ r0      * AS_LD + kb + tig]);
                afr[tm][1] = __float_as_uint(Sa[(r0 + 8) * AS_LD + kb + tig]);
                afr[tm][2] = __float_as_uint(Sa[ r0      * AS_LD + kb + tig + 4]);
                afr[tm][3] = __float_as_uint(Sa[(r0 + 8) * AS_LD + kb + tig + 4]);
            }
            #pragma unroll
            for (int tn = 0; tn < 8; tn++) {
                int n0 = wn * 64 + tn * 8 + g;
                bfr[tn][0] = __float_as_uint(Sb[(kb + tig)     * BS_LD + n0]);
                bfr[tn][1] = __float_as_uint(Sb[(kb + tig + 4) * BS_LD + n0]);
            }
            #pragma unroll
            for (int tm = 0; tm < 4; tm++)
                #pragma unroll
                for (int tn = 0; tn < 8; tn++)
                    asm volatile(
                        "mma.sync.aligned.m16n8k8.row.col.f32.tf32.tf32.f32 "
                        "{%0,%1,%2,%3}, {%4,%5,%6,%7}, {%8,%9}, {%0,%1,%2,%3};"
                        : "+f"(acc[tm][tn][0]), "+f"(acc[tm][tn][1]),
                          "+f"(acc[tm][tn][2]), "+f"(acc[tm][tn][3])
                        : "r"(afr[tm][0]), "r"(afr[tm][1]),
                          "r"(afr[tm][2]), "r"(afr[tm][3]),
                          "r"(bfr[tn][0]), "r"(bfr[tn][1]));
        }
        __syncthreads();
        if (kt + 2 < NT) issue(kt & 1, (kt + 2) * 32);
        cp_commit();
    }

    #pragma unroll
    for (int tm = 0; tm < 4; tm++) {
        int row0 = bm + wm * 64 + tm * 16 + g;
        #pragma unroll
        for (int tn = 0; tn < 8; tn++) {
            int col = bn + wn * 64 + tn * 8 + tig * 2;
            size_t off0 = (size_t)row0 * N + col;
            size_t off1 = (size_t)(row0 + 8) * N + col;
            float2 r0 = make_float2(acc[tm][tn][0], acc[tm][tn][1]);
            float2 r1 = make_float2(acc[tm][tn][2], acc[tm][tn][3]);
            if (resid) {
                float2 v0 = *(const float2*)(resid + off0);
                float2 v1 = *(const float2*)(resid + off1);
                r0.x += v0.x; r0.y += v0.y;
                r1.x += v1.x; r1.y += v1.y;
            }
            *(float2*)(C + off0) = r0;
            *(float2*)(C + off1) = r1;
        }
    }
}

// Epilogue GEMM: out = y @ wo + x
__global__ void __launch_bounds__(256) tgemm_kernel(
    const float* __restrict__ A, const float* __restrict__ B,
    float* __restrict__ C, const float* __restrict__ resid,
    int K, int N)
{
    extern __shared__ float dynsmem[];
    tgemm_body(A, B, C, resid, K, N, blockIdx.y * 128, blockIdx.x * BSN, dynsmem);
}

// Fused 4-way projection GEMM: same A (x_norm), blockIdx.z selects weight/output.
__global__ void __launch_bounds__(256) tgemm_proj4(
    const float* __restrict__ A,
    const float* __restrict__ B0, const float* __restrict__ B1,
    const float* __restrict__ B2, const float* __restrict__ B3,
    float* __restrict__ C0, float* __restrict__ C1,
    float* __restrict__ C2, float* __restrict__ C3)
{
    extern __shared__ float dynsmem[];
    const float* B; float* C;
    switch (blockIdx.z) {
        case 0: B = B0; C = C0; break;
        case 1: B = B1; C = C1; break;
        case 2: B = B2; C = C2; break;
        default: B = B3; C = C3; break;
    }
    tgemm_body(A, B, C, nullptr, Dq, Dq, blockIdx.y * 128, blockIdx.x * BSN, dynsmem);
}

// ---------------- beta/decay projections (round-8 version: 59us measured) ----------------
__global__ void ab_proj_kernel(const float* __restrict__ A_log,
                               const float* __restrict__ dt_bias)
{
    int row = blockIdx.x;
    int tid = threadIdx.x;  // 256
    __shared__ float4 xs4[256];
    xs4[tid] = ((const float4*)(g_xnorm + (size_t)row * Dq))[tid];
    __syncthreads();
    int warp = tid >> 5, lane = tid & 31;
    for (int j = warp; j < 32; j += 8) {
        int h = j & 15;
        const float4* W4 = (const float4*)(g_wt + (j >> 4) * (Hq * Dq) + h * Dq);
        float s = 0.f;
        #pragma unroll
        for (int it = 0; it < 8; it++) {
            float4 w  = W4[lane + 32 * it];
            float4 xv = xs4[lane + 32 * it];
            s += xv.x*w.x + xv.y*w.y + xv.z*w.z + xv.w*w.w;
        }
        #pragma unroll
        for (int o = 16; o; o >>= 1) s += __shfl_xor_sync(0xffffffffu, s, o);
        if (lane == 0) {
            if (j >= 16) {
                g_beta[(size_t)row * Hq + h] = 1.f / (1.f + expf(-s));
            } else {
                float dt = s + dt_bias[h];
                float sp = fmaxf(dt, 0.f) + log1pf(expf(-fabsf(dt)));  // stable softplus
                g_decay[(size_t)row * Hq + h] = expf(-expf(A_log[h]) * sp);
            }
        }
    }
}

// ---------------- depthwise causal conv (K=4) + SiLU (+ optional per-head L2 norm) ----------------
__global__ void conv_kernel(const float* __restrict__ qin, const float* __restrict__ kin,
                            const float* __restrict__ vin,
                            const float* __restrict__ qw, const float* __restrict__ kw,
                            const float* __restrict__ vw,
                            float* __restrict__ qout, float* __restrict__ kout,
                            float* __restrict__ vout)
{
    __shared__ float hs[16];
    const int mode = blockIdx.y;   // 0=q, 1=k, 2=v
    const float* in; const float* w; float* out;
    if (mode == 0)      { in = qin; w = qw; out = qout; }
    else if (mode == 1) { in = kin; w = kw; out = kout; }
    else                { in = vin; w = vw; out = vout; }

    int row = blockIdx.x;          // b*T + t
    int t = row & (Tq - 1);
    int c = threadIdx.x;           // 1024 threads = channels
    size_t base = (size_t)row * Dq + c;
    float x3 = in[base];
    float x2 = (t >= 1) ? in[base - 1 * Dq] : 0.f;
    float x1 = (t >= 2) ? in[base - 2 * Dq] : 0.f;
    float x0 = (t >= 3) ? in[base - 3 * Dq] : 0.f;
    float4 wv = ((const float4*)w)[c];     // w[c][0..3]
    float acc = x0 * wv.w + x1 * wv.z + x2 * wv.y + x3 * wv.x;
    float val = acc / (1.f + expf(-acc));  // SiLU
    if (mode == 2) {
        out[base] = val;
    } else {
        if (c < 16) hs[c] = 0.f;
        __syncthreads();
        float sq = val * val;
        #pragma unroll
        for (int o = 16; o; o >>= 1) sq += __shfl_xor_sync(0xffffffffu, sq, o);
        if ((c & 31) == 0) atomicAdd(&hs[c >> 6], sq);
        __syncthreads();
        float n = sqrtf(hs[c >> 6]);
        float r = val / fmaxf(n, 1e-12f);
        if (mode == 0) r *= 0.125f;  // DK^-0.5
        out[base] = r;
    }
}

// ---------------- gated delta-rule scan ----------------
#define TS 16
__global__ void __launch_bounds__(128) scan_kernel()
{
    int bid = blockIdx.x;
    int bh = bid >> 2, dvq = bid & 3;
    int b = bh >> 4, h = bh & 15;
    int tid = threadIdx.x;
    int oct = tid & 7, dvl = tid >> 3;   // dvl in [0,16)

    __shared__ float sk[TS][64], sq[TS][64], sv[TS][16], sb[TS], sd[TS];
    __shared__ float sop[TS][16][8];     // per-oct partial outputs

    float s[8];
    #pragma unroll
    for (int i = 0; i < 8; i++) s[i] = 0.f;

    size_t baseRow = (size_t)b * Tq;
    int hoff = h * 64;

    for (int t0 = 0; t0 < Tq; t0 += TS) {
        for (int m = tid; m < TS * 64; m += 128) {
            int tl = m >> 6, ci = m & 63;
            size_t goff = (baseRow + t0 + tl) * (size_t)Dq + hoff + ci;
            sk[tl][ci] = g_kc[goff];
            sq[tl][ci] = g_qc[goff];
        }
        for (int m = tid; m < TS * 16; m += 128) {
            int tl = m >> 4, ci = m & 15;
            sv[tl][ci] = g_vc[(baseRow + t0 + tl) * (size_t)Dq + hoff + dvq * 16 + ci];
        }
        if (tid < TS) {
            sb[tid] = g_beta [(baseRow + t0 + tid) * Hq + h];
            sd[tid] = g_decay[(baseRow + t0 + tid) * Hq + h];
        }
        __syncthreads();   // A

        for (int tl = 0; tl < TS; tl++) {
            float k[8], q[8];
            *(float4*)&k[0] = *(const float4*)&sk[tl][oct * 8];
            *(float4*)&k[4] = *(const float4*)&sk[tl][oct * 8 + 4];
            *(float4*)&q[0] = *(const float4*)&sq[tl][oct * 8];
            *(float4*)&q[4] = *(const float4*)&sq[tl][oct * 8 + 4];
            float v  = sv[tl][dvl];
            float bt = sb[tl];
            float dc = sd[tl];
            float c0 = 0.f, c1 = 0.f;
            #pragma unroll
            for (int i = 0; i < 4; i++) {
                c0 = fmaf(k[i],     s[i],     c0);
                c1 = fmaf(k[i + 4], s[i + 4], c1);
            }
            float c = c0 + c1;
            c += __shfl_xor_sync(0xffffffffu, c, 1);
            c += __shfl_xor_sync(0xffffffffu, c, 2);
            c += __shfl_xor_sync(0xffffffffu, c, 4);
            float g = bt * (v - dc * c);
            float o0 = 0.f, o1 = 0.f;
            #pragma unroll
            for (int i = 0; i < 8; i++) s[i] = fmaf(dc, s[i], g * k[i]);
            #pragma unroll
            for (int i = 0; i < 4; i++) {
                o0 = fmaf(q[i],     s[i],     o0);
                o1 = fmaf(q[i + 4], s[i + 4], o1);
            }
            sop[tl][dvl][oct] = o0 + o1;   // partial; reduced at dump
        }
        __syncthreads();   // B
        for (int m = tid; m < TS * 16; m += 128) {
            int tl = m >> 4, ci = m & 15;
            float4 p0 = *(const float4*)&sop[tl][ci][0];
            float4 p1 = *(const float4*)&sop[tl][ci][4];
            float o = (p0.x + p0.y + p0.z + p0.w) + (p1.x + p1.y + p1.z + p1.w);
            g_o[(baseRow + t0 + tl) * (size_t)Dq + hoff + dvq * 16 + ci] = o;
        }
    }
}

// ---------------- output gating: y = rmsnorm_dv(o) * o_scale * silu(gate) ----------------
__global__ void gate_kernel(const float* __restrict__ oscale)
{
    __shared__ float hs[16];
    int row = blockIdx.x;
    int c = threadIdx.x;  // 1024
    size_t off = (size_t)row * Dq + c;
    float ov = g_o[off];
    if (c < 16) hs[c] = 0.f;
    __syncthreads();
    float sq = ov * ov;
    #pragma unroll
    for (int o = 16; o; o >>= 1) sq += __shfl_xor_sync(0xffffffffu, sq, o);
    if ((c & 31) == 0) atomicAdd(&hs[c >> 6], sq);
    __syncthreads();
    float inv = rsqrtf(hs[c >> 6] * (1.f / 64.f) + 1e-5f);
    float gt = g_g[off];
    float si = gt / (1.f + expf(-gt));
    g_y[off] = ov * inv * oscale[c & 63] * si;
}

// ---------------- launch ----------------
extern "C" void kernel_launch(void* const* d_in, const int* in_sizes, int n_in,
                              void* d_out, int out_size)
{
    const float* x          = (const float*)d_in[0];
    const float* norm_scale = (const float*)d_in[1];
    const float* wq         = (const float*)d_in[2];
    const float* w_k        = (const float*)d_in[3];
    const float* w_v        = (const float*)d_in[4];
    const float* q_conv_w   = (const float*)d_in[5];
    const float* k_conv_w   = (const float*)d_in[6];
    const float* v_conv_w   = (const float*)d_in[7];
    const float* a_proj     = (const float*)d_in[8];
    const float* A_log      = (const float*)d_in[9];
    const float* dt_bias    = (const float*)d_in[10];
    const float* b_proj     = (const float*)d_in[11];
    const float* g_proj     = (const float*)d_in[12];
    const float* o_norm     = (const float*)d_in[13];
    const float* wo         = (const float*)d_in[14];
    float* out              = (float*)d_out;

    float *p_xnorm, *p_q, *p_k, *p_v, *p_g, *p_qc, *p_kc, *p_vc, *p_y;
    cudaGetSymbolAddress((void**)&p_xnorm, g_xnorm);
    cudaGetSymbolAddress((void**)&p_q,  g_q);
    cudaGetSymbolAddress((void**)&p_k,  g_k);
    cudaGetSymbolAddress((void**)&p_v,  g_v);
    cudaGetSymbolAddress((void**)&p_g,  g_g);
    cudaGetSymbolAddress((void**)&p_qc, g_qc);
    cudaGetSymbolAddress((void**)&p_kc, g_kc);
    cudaGetSymbolAddress((void**)&p_vc, g_vc);
    cudaGetSymbolAddress((void**)&p_y,  g_y);

    cudaFuncSetAttribute(tgemm_proj4, cudaFuncAttributeMaxDynamicSharedMemorySize, GEMM_SMEM_BYTES);
    cudaFuncSetAttribute(tgemm_kernel, cudaFuncAttributeMaxDynamicSharedMemorySize, GEMM_SMEM_BYTES);

    // Launch order chosen so tgemm_proj4 is the 4th launch -> gets ncu-captured.
    transpose_ab<<<64, 256>>>(a_proj, b_proj);
    rmsnorm_kernel<<<MT, 256>>>(x, norm_scale);
    ab_proj_kernel<<<MT, 256>>>(A_log, dt_bias);

    dim3 proj_grid(Dq / BSN, MT / 128, 4);  // (4, 64, 4)
    tgemm_proj4<<<proj_grid, 256, GEMM_SMEM_BYTES>>>(p_xnorm, wq, w_k, w_v, g_proj,
                                                     p_q, p_k, p_v, p_g);

    dim3 conv_grid(MT, 3);
    conv_kernel<<<conv_grid, 1024>>>(p_q, p_k, p_v,
                                     q_conv_w, k_conv_w, v_conv_w,
                                     p_qc, p_kc, p_vc);

    scan_kernel<<<Bq * Hq * 4, 128>>>();

    gate_kernel<<<MT, 1024>>>(o_norm);

    dim3 gemm_grid(Dq / BSN, MT / 128);     // (4, 64)
    tgemm_kernel<<<gemm_grid, 256, GEMM_SMEM_BYTES>>>(p_y, wo, out, x, Dq, Dq);
}